// round 8
// baseline (speedup 1.0000x reference)
#include <cuda_runtime.h>
#include <math.h>

#define BATCH 64
#define TT 512
#define II 512
#define HH 512
#define NG 8      // batch groups (8 batches each)
#define CPG 16    // CTAs per group (32 cols each)

typedef unsigned long long ull;

__device__ __forceinline__ ull pack2(float x, float y) {
    ull r; asm("mov.b64 %0, {%1, %2};" : "=l"(r) : "f"(x), "f"(y)); return r;
}
__device__ __forceinline__ void unpack2(ull v, float& x, float& y) {
    asm("mov.b64 {%0, %1}, %2;" : "=f"(x), "=f"(y) : "l"(v));
}
__device__ __forceinline__ ull ffma2(ull a, ull b, ull c) {
    ull d; asm("fma.rn.f32x2 %0, %1, %2, %3;" : "=l"(d) : "l"(a), "l"(b), "l"(c)); return d;
}
__device__ __forceinline__ ull fadd2(ull a, ull b) {
    ull d; asm("add.rn.f32x2 %0, %1, %2;" : "=l"(d) : "l"(a), "l"(b)); return d;
}
__device__ __forceinline__ unsigned ld_acq(const unsigned* p) {
    unsigned v; asm volatile("ld.acquire.gpu.global.u32 %0, [%1];" : "=r"(v) : "l"(p) : "memory");
    return v;
}
__device__ __forceinline__ void st_rel(unsigned* p, unsigned v) {
    asm volatile("st.release.gpu.global.u32 [%0], %1;" :: "l"(p), "r"(v) : "memory");
}
__device__ __forceinline__ void red_rel_add1(unsigned* p) {
    asm volatile("red.release.gpu.global.add.u32 [%0], 1;" :: "l"(p) : "memory");
}
__device__ __forceinline__ float tanh_fast(float x) {
    float ax = fabsf(x);
    if (ax < 0.04f) return x * (1.0f - 0.3333333f * x * x);
    float e = __expf(2.0f * x);
    return 1.0f - __fdividef(2.0f, e + 1.0f);
}

// persistent state: per-timestep h buffers (no reuse -> L1-safe), flags, done
__device__ float    g_h[TT][HH][BATCH];     // 64MB
__device__ unsigned g_flag[NG * 32];        // 16 flags per group, 128B apart
__device__ unsigned g_done[NG * 32];

// ---------------------------------------------------------------------------
// Phase 1: xw = X @ Wx + bx + bh  (unchanged R2 version)
// ---------------------------------------------------------------------------
__global__ __launch_bounds__(256, 2) void gemm_xw_kernel(
    const float* __restrict__ X, const float* __restrict__ Wx,
    const float* __restrict__ bx, const float* __restrict__ bh,
    float* __restrict__ out)
{
    __shared__ float As[2][8][128];
    __shared__ float Bs[2][8][128];

    const int tid = threadIdx.x;
    const int bm = blockIdx.y * 128, bn = blockIdx.x * 128;
    const int ty = tid >> 4, tx = tid & 15;
    const int arow = tid >> 1, akc = (tid & 1) * 4;
    const int brow = tid >> 5, bcc = (tid & 31) * 4;

    const float* Ag = X + (size_t)(bm + arow) * II + akc;
    const float* Bg = Wx + (size_t)brow * HH + bn + bcc;

    {
        float4 av = *(const float4*)Ag;
        float4 bv = *(const float4*)Bg;
        As[0][akc+0][arow] = av.x; As[0][akc+1][arow] = av.y;
        As[0][akc+2][arow] = av.z; As[0][akc+3][arow] = av.w;
        *(float4*)&Bs[0][brow][bcc] = bv;
    }
    __syncthreads();

    ull acc[8][4];
#pragma unroll
    for (int i = 0; i < 8; i++)
#pragma unroll
        for (int j = 0; j < 4; j++) acc[i][j] = 0ull;

    const int NT = II / 8;
    for (int kt = 0; kt < NT; kt++) {
        const int cur = kt & 1;
        float4 av, bv;
        if (kt + 1 < NT) {
            av = *(const float4*)(Ag + (kt + 1) * 8);
            bv = *(const float4*)(Bg + (size_t)(kt + 1) * 8 * HH);
        }
#pragma unroll
        for (int kk = 0; kk < 8; kk++) {
            float4 a0 = *(const float4*)&As[cur][kk][ty * 8];
            float4 a1 = *(const float4*)&As[cur][kk][ty * 8 + 4];
            float4 b0 = *(const float4*)&Bs[cur][kk][tx * 8];
            float4 b1 = *(const float4*)&Bs[cur][kk][tx * 8 + 4];
            ull bp[4] = { pack2(b0.x,b0.y), pack2(b0.z,b0.w),
                          pack2(b1.x,b1.y), pack2(b1.z,b1.w) };
            float aa[8] = { a0.x,a0.y,a0.z,a0.w, a1.x,a1.y,a1.z,a1.w };
#pragma unroll
            for (int i = 0; i < 8; i++) {
                ull ap = pack2(aa[i], aa[i]);
#pragma unroll
                for (int j = 0; j < 4; j++) acc[i][j] = ffma2(ap, bp[j], acc[i][j]);
            }
        }
        if (kt + 1 < NT) {
            const int nxt = cur ^ 1;
            __syncthreads();
            As[nxt][akc+0][arow] = av.x; As[nxt][akc+1][arow] = av.y;
            As[nxt][akc+2][arow] = av.z; As[nxt][akc+3][arow] = av.w;
            *(float4*)&Bs[nxt][brow][bcc] = bv;
            __syncthreads();
        }
    }

    const int n0 = bn + tx * 8;
    float bias[8];
#pragma unroll
    for (int j = 0; j < 8; j++) bias[j] = bx[n0 + j] + bh[n0 + j];
#pragma unroll
    for (int i = 0; i < 8; i++) {
        const int m = bm + ty * 8 + i;
        float o[8];
#pragma unroll
        for (int j = 0; j < 4; j++) unpack2(acc[i][j], o[j*2], o[j*2+1]);
        float4 v0 = make_float4(o[0]+bias[0], o[1]+bias[1], o[2]+bias[2], o[3]+bias[3]);
        float4 v1 = make_float4(o[4]+bias[4], o[5]+bias[5], o[6]+bias[6], o[7]+bias[7]);
        *(float4*)&out[(size_t)m * HH + n0]     = v0;
        *(float4*)&out[(size_t)m * HH + n0 + 4] = v1;
    }
}

// ---------------------------------------------------------------------------
// Phase 2: recurrence. 128 CTAs x 256 thr. CTA (g, cg): 8 batches x 32 cols.
// Warp w owns 4 cols x 8 batches x ALL 512 k; lane = 16-wide k chunk.
// h read directly from per-step global buffers (no smem staging).
// Reduction entirely in-warp (5 shfl rounds). Sync = per-CTA release flags.
// ---------------------------------------------------------------------------
__global__ __launch_bounds__(256, 1) void rnn_kernel(
    const float* __restrict__ Wh, float* __restrict__ out)
{
    const int tid  = threadIdx.x;
    const int lane = tid & 31;
    const int w    = tid >> 5;
    const int cg   = blockIdx.x & 15;
    const int g    = blockIdx.x >> 4;
    const int jbase = cg * 32;
    const int bbase = g * 8;
    const int col0  = jbase + w * 4;

    // weights: w2[i][c] = dup(Wh[lane*16+i][col0+c])
    ull w2[16][4];
#pragma unroll
    for (int i = 0; i < 16; i++) {
        float4 wv = *(const float4*)&Wh[(size_t)(lane * 16 + i) * HH + col0];
        w2[i][0] = pack2(wv.x, wv.x);
        w2[i][1] = pack2(wv.y, wv.y);
        w2[i][2] = pack2(wv.z, wv.z);
        w2[i][3] = pack2(wv.w, wv.w);
    }

    // final mapping after fold: m = bitrev4(lane&15)
    const int l4 = lane & 15;
    const int m  = ((l4 & 1) << 3) | ((l4 & 2) << 1) | ((l4 & 4) >> 1) | ((l4 & 8) >> 3);
    const int fc = m >> 2, fp = m & 3, fe = lane >> 4;
    const int fj = col0 + fc;
    const int fb = bbase + fp * 2 + fe;

    unsigned* flags = &g_flag[g * 32];
    const unsigned* myfl = &flags[lane >> 1];   // lane's h-band source CTA

    float* mem = out;
    float* hid = out + (size_t)BATCH * TT * HH;

    for (int t = 0; t < TT; t++) {
        float xw = __ldg(&mem[((size_t)fb * TT + t) * HH + fj]);

        ull acc[4][4];
#pragma unroll
        for (int c = 0; c < 4; c++)
#pragma unroll
            for (int p = 0; p < 4; p++) acc[c][p] = 0ull;

        if (t > 0) {
            // each lane acquires exactly its source CTA's flag
            while (!__all_sync(0xFFFFFFFFu, ld_acq(myfl) >= (unsigned)t)) { }

            const float* hrow = &g_h[t][lane * 16][bbase];
#pragma unroll 4
            for (int i = 0; i < 16; i++) {
                ulonglong2 u0 = *(const ulonglong2*)(hrow + (size_t)i * BATCH);
                ulonglong2 u1 = *(const ulonglong2*)(hrow + (size_t)i * BATCH + 4);
#pragma unroll
                for (int c = 0; c < 4; c++) {
                    acc[c][0] = ffma2(u0.x, w2[i][c], acc[c][0]);
                    acc[c][1] = ffma2(u0.y, w2[i][c], acc[c][1]);
                    acc[c][2] = ffma2(u1.x, w2[i][c], acc[c][2]);
                    acc[c][3] = ffma2(u1.y, w2[i][c], acc[c][3]);
                }
            }
        }

        // in-warp fold: 16 pair-accs over 16 k-lanes, then pair split over bit4
        ull v[16];
#pragma unroll
        for (int i = 0; i < 16; i++) v[i] = acc[i >> 2][i & 3];
#pragma unroll
        for (int r = 0; r < 4; r++) {
            const int M = 1 << r, N = 8 >> r;
#pragma unroll
            for (int i = 0; i < N; i++) {
                ull give = (lane & M) ? v[i] : v[i + N];
                ull got  = __shfl_xor_sync(0xFFFFFFFFu, give, M);
                ull keep = (lane & M) ? v[i + N] : v[i];
                v[i] = fadd2(keep, got);
            }
        }
        ull s = fadd2(v[0], __shfl_xor_sync(0xFFFFFFFFu, v[0], 16));
        float sx, sy; unpack2(s, sx, sy);
        float rsum = (lane & 16) ? sy : sx;

        float val = tanh_fast(xw + rsum);
        mem[((size_t)fb * TT + t) * HH + fj] = val;
        if (t == TT - 1) {
            hid[(size_t)fb * HH + fj] = val;
        } else {
            g_h[t + 1][fj][fb] = val;
            __syncthreads();
            if (tid == 0) st_rel(&flags[cg], (unsigned)(t + 1));
        }
    }

    // replay reset: group handshake, then cg0 zeroes flags
    __syncthreads();
    if (tid == 0) {
        red_rel_add1(&g_done[g * 32]);
        if (cg == 0) {
            while (ld_acq(&g_done[g * 32]) < (unsigned)CPG) { }
#pragma unroll
            for (int i = 0; i < CPG; i++) flags[i] = 0u;
            g_done[g * 32] = 0u;
        }
    }
}

// ---------------------------------------------------------------------------
extern "C" void kernel_launch(void* const* d_in, const int* in_sizes, int n_in,
                              void* d_out, int out_size) {
    const float* x  = (const float*)d_in[0];
    const float* Wx = (const float*)d_in[1];
    const float* Wh = (const float*)d_in[2];
    const float* bx = (const float*)d_in[3];
    const float* bh = (const float*)d_in[4];
    float* out = (float*)d_out;

    dim3 ggrid(HH / 128, (BATCH * TT) / 128);
    gemm_xw_kernel<<<ggrid, 256>>>(x, Wx, bx, bh, out);
    rnn_kernel<<<128, 256>>>(Wh, out);
}

// round 9
// speedup vs baseline: 1.2920x; 1.2920x over previous
#include <cuda_runtime.h>
#include <math.h>

#define BATCH 64
#define TT 512
#define II 512
#define HH 512
#define NG 8      // batch groups (8 batches each)
#define CPG 16    // CTAs per group (32 cols each)

typedef unsigned long long ull;

__device__ __forceinline__ ull pack2(float x, float y) {
    ull r; asm("mov.b64 %0, {%1, %2};" : "=l"(r) : "f"(x), "f"(y)); return r;
}
__device__ __forceinline__ void unpack2(ull v, float& x, float& y) {
    asm("mov.b64 {%0, %1}, %2;" : "=f"(x), "=f"(y) : "l"(v));
}
__device__ __forceinline__ ull ffma2(ull a, ull b, ull c) {
    ull d; asm("fma.rn.f32x2 %0, %1, %2, %3;" : "=l"(d) : "l"(a), "l"(b), "l"(c)); return d;
}
__device__ __forceinline__ ull fadd2(ull a, ull b) {
    ull d; asm("add.rn.f32x2 %0, %1, %2;" : "=l"(d) : "l"(a), "l"(b)); return d;
}
__device__ __forceinline__ unsigned ld_acq(const unsigned* p) {
    unsigned v; asm volatile("ld.acquire.gpu.global.u32 %0, [%1];" : "=r"(v) : "l"(p) : "memory");
    return v;
}
__device__ __forceinline__ void st_rel(unsigned* p, unsigned v) {
    asm volatile("st.release.gpu.global.u32 [%0], %1;" :: "l"(p), "r"(v) : "memory");
}
__device__ __forceinline__ void red_rel_add1(unsigned* p) {
    asm volatile("red.release.gpu.global.add.u32 [%0], 1;" :: "l"(p) : "memory");
}
__device__ __forceinline__ float tanh_fast(float x) {
    float ax = fabsf(x);
    if (ax < 0.04f) return x * (1.0f - 0.3333333f * x * x);
    float e = __expf(2.0f * x);
    return 1.0f - __fdividef(2.0f, e + 1.0f);
}

// persistent state: h transposed [j][b] ping-pong; per-CTA flags; done counters
__device__ float    g_hT[2][HH][BATCH];
__device__ unsigned g_flag[NG * 32];    // 16 flags per group (one line), 128B apart
__device__ unsigned g_done[NG * 32];

// ---------------------------------------------------------------------------
// Phase 1: xw = X @ Wx + bx + bh  (unchanged R2 version)
// ---------------------------------------------------------------------------
__global__ __launch_bounds__(256, 2) void gemm_xw_kernel(
    const float* __restrict__ X, const float* __restrict__ Wx,
    const float* __restrict__ bx, const float* __restrict__ bh,
    float* __restrict__ out)
{
    __shared__ float As[2][8][128];
    __shared__ float Bs[2][8][128];

    const int tid = threadIdx.x;
    const int bm = blockIdx.y * 128, bn = blockIdx.x * 128;
    const int ty = tid >> 4, tx = tid & 15;
    const int arow = tid >> 1, akc = (tid & 1) * 4;
    const int brow = tid >> 5, bcc = (tid & 31) * 4;

    const float* Ag = X + (size_t)(bm + arow) * II + akc;
    const float* Bg = Wx + (size_t)brow * HH + bn + bcc;

    {
        float4 av = *(const float4*)Ag;
        float4 bv = *(const float4*)Bg;
        As[0][akc+0][arow] = av.x; As[0][akc+1][arow] = av.y;
        As[0][akc+2][arow] = av.z; As[0][akc+3][arow] = av.w;
        *(float4*)&Bs[0][brow][bcc] = bv;
    }
    __syncthreads();

    ull acc[8][4];
#pragma unroll
    for (int i = 0; i < 8; i++)
#pragma unroll
        for (int j = 0; j < 4; j++) acc[i][j] = 0ull;

    const int NT = II / 8;
    for (int kt = 0; kt < NT; kt++) {
        const int cur = kt & 1;
        float4 av, bv;
        if (kt + 1 < NT) {
            av = *(const float4*)(Ag + (kt + 1) * 8);
            bv = *(const float4*)(Bg + (size_t)(kt + 1) * 8 * HH);
        }
#pragma unroll
        for (int kk = 0; kk < 8; kk++) {
            float4 a0 = *(const float4*)&As[cur][kk][ty * 8];
            float4 a1 = *(const float4*)&As[cur][kk][ty * 8 + 4];
            float4 b0 = *(const float4*)&Bs[cur][kk][tx * 8];
            float4 b1 = *(const float4*)&Bs[cur][kk][tx * 8 + 4];
            ull bp[4] = { pack2(b0.x,b0.y), pack2(b0.z,b0.w),
                          pack2(b1.x,b1.y), pack2(b1.z,b1.w) };
            float aa[8] = { a0.x,a0.y,a0.z,a0.w, a1.x,a1.y,a1.z,a1.w };
#pragma unroll
            for (int i = 0; i < 8; i++) {
                ull ap = pack2(aa[i], aa[i]);
#pragma unroll
                for (int j = 0; j < 4; j++) acc[i][j] = ffma2(ap, bp[j], acc[i][j]);
            }
        }
        if (kt + 1 < NT) {
            const int nxt = cur ^ 1;
            __syncthreads();
            As[nxt][akc+0][arow] = av.x; As[nxt][akc+1][arow] = av.y;
            As[nxt][akc+2][arow] = av.z; As[nxt][akc+3][arow] = av.w;
            *(float4*)&Bs[nxt][brow][bcc] = bv;
            __syncthreads();
        }
    }

    const int n0 = bn + tx * 8;
    float bias[8];
#pragma unroll
    for (int j = 0; j < 8; j++) bias[j] = bx[n0 + j] + bh[n0 + j];
#pragma unroll
    for (int i = 0; i < 8; i++) {
        const int m = bm + ty * 8 + i;
        float o[8];
#pragma unroll
        for (int j = 0; j < 4; j++) unpack2(acc[i][j], o[j*2], o[j*2+1]);
        float4 v0 = make_float4(o[0]+bias[0], o[1]+bias[1], o[2]+bias[2], o[3]+bias[3]);
        float4 v1 = make_float4(o[4]+bias[4], o[5]+bias[5], o[6]+bias[6], o[7]+bias[7]);
        *(float4*)&out[(size_t)m * HH + n0]     = v0;
        *(float4*)&out[(size_t)m * HH + n0 + 4] = v1;
    }
}

// ---------------------------------------------------------------------------
// Phase 2: recurrence. 128 CTAs x 256 threads. CTA (g 0..7, cg 0..15):
// 8 batches x 32 cols. Sync = per-CTA flag words (st.release / ld.acquire),
// 16 flags per group in ONE cache line. Release after a 128-thread named
// barrier among the reducer warps; poll is per-warp (no block serialization).
// Compute core identical to R7: smem-staged transposed h, zero-pack FFMA2.
// ---------------------------------------------------------------------------
#define PIDX(l, w_, p_) ((l) * 33 + (w_) * 4 + (p_))

__global__ __launch_bounds__(256, 1) void rnn_kernel(
    const float* __restrict__ Wh, float* __restrict__ out)
{
    __shared__ float h_Ts[HH * 8];        // [k][8 batches], 16KB
    __shared__ ull   part[32 * 33];       // padded stride 33, ~8.4KB

    const int tid  = threadIdx.x;
    const int lane = tid & 31;
    const int w    = tid >> 5;
    const int jq   = lane & 15;
    const int hl   = lane >> 4;
    const int kt   = (w << 1) | hl;       // 0..15
    const int cg   = blockIdx.x & 15;
    const int g    = blockIdx.x >> 4;
    const int jbase = cg * 32;
    const int bbase = g * 8;

    // weights: w2[i][c] = dup(Wh[kt*32+i][jbase + jq*2 + c])
    ull w2[32][2];
#pragma unroll
    for (int i = 0; i < 32; i++) {
        float2 wv = *(const float2*)&Wh[(size_t)(kt * 32 + i) * HH + jbase + jq * 2];
        w2[i][0] = pack2(wv.x, wv.x);
        w2[i][1] = pack2(wv.y, wv.y);
    }

    // reducer mapping (tid < 128): col rj, batch pair rp
    const int rjc = tid & 31;
    const int rp  = (tid >> 5) & 3;
    const int rb0 = bbase + rp * 2;
    const int rj  = jbase + rjc;
    const int rlane = ((rjc & 1) << 4) | (rjc >> 1);
    const bool is_red = (tid < 128);

    float* mem = out;
    float* hid = out + (size_t)BATCH * TT * HH;
    unsigned* flags = &g_flag[g * 32];
    const unsigned* myfl = &flags[lane & 15];

    for (int t = 0; t < TT; t++) {
        float xw0 = 0.f, xw1 = 0.f;
        if (is_red) {
            xw0 = __ldg(&mem[((size_t)rb0 * TT + t) * HH + rj]);
            xw1 = __ldg(&mem[((size_t)(rb0 + 1) * TT + t) * HH + rj]);
        }

        ull acc[2][4];
#pragma unroll
        for (int p = 0; p < 4; p++) { acc[0][p] = 0ull; acc[1][p] = 0ull; }

        if (t > 0) {
            // per-warp acquire: all 16 group CTAs published h_t
            while (!__all_sync(0xFFFFFFFFu, ld_acq(myfl) >= (unsigned)t)) { }

            // stage h_t: g_hT[t&1][k][bbase..+8) -> h_Ts[k][8]
            const float* gsrc = &g_hT[t & 1][0][0];
#pragma unroll
            for (int i = 0; i < 4; i++) {
                int e = tid + i * 256;            // 0..1023
                int row = e >> 1, q = e & 1;
                float4 v = __ldcg((const float4*)&gsrc[row * BATCH + bbase + q * 4]);
                *(float4*)&h_Ts[row * 8 + q * 4] = v;
            }
            __syncthreads();

            const ulonglong2* hb = (const ulonglong2*)&h_Ts[kt * 32 * 8];
#pragma unroll
            for (int i = 0; i < 32; i++) {
                ulonglong2 u0 = hb[2 * i], u1 = hb[2 * i + 1];
                ull w0 = w2[i][0], w1 = w2[i][1];
                acc[0][0] = ffma2(u0.x, w0, acc[0][0]);
                acc[0][1] = ffma2(u0.y, w0, acc[0][1]);
                acc[0][2] = ffma2(u1.x, w0, acc[0][2]);
                acc[0][3] = ffma2(u1.y, w0, acc[0][3]);
                acc[1][0] = ffma2(u0.x, w1, acc[1][0]);
                acc[1][1] = ffma2(u0.y, w1, acc[1][1]);
                acc[1][2] = ffma2(u1.x, w1, acc[1][2]);
                acc[1][3] = ffma2(u1.y, w1, acc[1][3]);
            }
        }

        // fold across lane bit 4
        ull v[4];
#pragma unroll
        for (int p = 0; p < 4; p++) {
            ull give = hl ? acc[0][p] : acc[1][p];
            ull got  = __shfl_xor_sync(0xFFFFFFFFu, give, 16);
            ull keep = hl ? acc[1][p] : acc[0][p];
            v[p] = fadd2(keep, got);
        }
#pragma unroll
        for (int p = 0; p < 4; p++) part[PIDX(lane, w, p)] = v[p];
        __syncthreads();

        if (is_red) {
            ull s = part[PIDX(rlane, 0, rp)];
#pragma unroll
            for (int ww = 1; ww < 8; ww++) s = fadd2(s, part[PIDX(rlane, ww, rp)]);
            float a0, a1; unpack2(s, a0, a1);
            float r0 = tanh_fast(xw0 + a0);
            float r1 = tanh_fast(xw1 + a1);
            mem[((size_t)rb0 * TT + t) * HH + rj] = r0;
            mem[((size_t)(rb0 + 1) * TT + t) * HH + rj] = r1;
            *(float2*)&g_hT[(t + 1) & 1][rj][rb0] = make_float2(r0, r1);
            if (t == TT - 1) {
                hid[(size_t)rb0 * HH + rj] = r0;
                hid[(size_t)(rb0 + 1) * HH + rj] = r1;
            }
            if (t < TT - 1) {
                // order the 4 reducer warps' h stores, then publish once
                asm volatile("bar.sync 1, 128;" ::: "memory");
                if (tid == 0) st_rel(&flags[cg], (unsigned)(t + 1));
            }
        }
    }

    // replay reset: group handshake, then cg0 zeroes flags
    __syncthreads();
    if (tid == 0) {
        red_rel_add1(&g_done[g * 32]);
        if (cg == 0) {
            while (ld_acq(&g_done[g * 32]) < (unsigned)CPG) { }
#pragma unroll
            for (int i = 0; i < CPG; i++) flags[i] = 0u;
            g_done[g * 32] = 0u;
        }
    }
}

// ---------------------------------------------------------------------------
extern "C" void kernel_launch(void* const* d_in, const int* in_sizes, int n_in,
                              void* d_out, int out_size) {
    const float* x  = (const float*)d_in[0];
    const float* Wx = (const float*)d_in[1];
    const float* Wh = (const float*)d_in[2];
    const float* bx = (const float*)d_in[3];
    const float* bh = (const float*)d_in[4];
    float* out = (float*)d_out;

    dim3 ggrid(HH / 128, (BATCH * TT) / 128);
    gemm_xw_kernel<<<ggrid, 256>>>(x, Wx, bx, bh, out);
    rnn_kernel<<<128, 256>>>(Wh, out);
}

// round 10
// speedup vs baseline: 2.5167x; 1.9480x over previous
#include <cuda_runtime.h>
#include <math.h>

#define BATCH 64
#define TT 512
#define II 512
#define HH 512
#define NG 8
#define CPG 16

typedef unsigned long long ull;

__device__ __forceinline__ ull pack2(float x, float y) {
    ull r; asm("mov.b64 %0, {%1, %2};" : "=l"(r) : "f"(x), "f"(y)); return r;
}
__device__ __forceinline__ void unpack2(ull v, float& x, float& y) {
    asm("mov.b64 {%0, %1}, %2;" : "=f"(x), "=f"(y) : "l"(v));
}
__device__ __forceinline__ ull ffma2(ull a, ull b, ull c) {
    ull d; asm("fma.rn.f32x2 %0, %1, %2, %3;" : "=l"(d) : "l"(a), "l"(b), "l"(c)); return d;
}
__device__ __forceinline__ ull fadd2(ull a, ull b) {
    ull d; asm("add.rn.f32x2 %0, %1, %2;" : "=l"(d) : "l"(a), "l"(b)); return d;
}
__device__ __forceinline__ unsigned ld_acq(const unsigned* p) {
    unsigned v; asm volatile("ld.acquire.gpu.global.u32 %0, [%1];" : "=r"(v) : "l"(p) : "memory");
    return v;
}
__device__ __forceinline__ void red_rel_add1(unsigned* p) {
    asm volatile("red.release.gpu.global.add.u32 [%0], 1;" :: "l"(p) : "memory");
}
__device__ __forceinline__ float tanh_fast(float x) {
    float ax = fabsf(x);
    if (ax < 0.04f) return x * (1.0f - 0.3333333f * x * x);
    float e = __expf(2.0f * x);
    return 1.0f - __fdividef(2.0f, e + 1.0f);
}
__device__ __forceinline__ unsigned f2tf(float x) {
    unsigned r; asm("cvt.rna.tf32.f32 %0, %1;" : "=r"(r) : "f"(x)); return r;
}
__device__ __forceinline__ void mma_tf32(float* d, const unsigned* a, const unsigned* b) {
    asm volatile(
        "mma.sync.aligned.m16n8k8.row.col.f32.tf32.tf32.f32 "
        "{%0,%1,%2,%3}, {%4,%5,%6,%7}, {%8,%9}, {%0,%1,%2,%3};"
        : "+f"(d[0]), "+f"(d[1]), "+f"(d[2]), "+f"(d[3])
        : "r"(a[0]), "r"(a[1]), "r"(a[2]), "r"(a[3]), "r"(b[0]), "r"(b[1]));
}

// persistent state (unchanged from R7)
__device__ float    g_hT[2][HH][BATCH];
__device__ unsigned g_bar[NG * 32];

// ---------------------------------------------------------------------------
// Phase 1: TF32 tensor-core GEMM with 3xTF32 split.
// CTA tile 128x128, 8 warps (4Mx2N), warp tile 32x64, BK=32, double-buffered.
// A stored transposed [k][m] stride 137; B [k][n] stride 136.
// ---------------------------------------------------------------------------
#define SA 137
#define SB 136
#define ABUF (32 * SA)
#define BBUF (32 * SB)
#define GSMEM ((2 * ABUF + 2 * BBUF) * 4)

extern __shared__ float gs[];

__global__ __launch_bounds__(256, 1) void gemm_tf32_kernel(
    const float* __restrict__ X, const float* __restrict__ Wx,
    const float* __restrict__ bx, const float* __restrict__ bh,
    float* __restrict__ out)
{
    float* Asm = gs;
    float* Bsm = gs + 2 * ABUF;

    const int tid = threadIdx.x;
    const int lane = tid & 31, wid = tid >> 5;
    const int wm = wid & 3, wn = wid >> 2;
    const int g = lane >> 2, t = lane & 3;
    const int bm = blockIdx.y * 128, bn = blockIdx.x * 128;

    float4 av[4], bv[4];
#pragma unroll
    for (int i = 0; i < 4; i++) {
        int fa = tid + i * 256;
        av[i] = *(const float4*)(X + (size_t)(bm + (fa >> 3)) * II + ((fa & 7) << 2));
        bv[i] = *(const float4*)(Wx + (size_t)(fa >> 5) * HH + bn + ((fa & 31) << 2));
    }
#pragma unroll
    for (int i = 0; i < 4; i++) {
        int fa = tid + i * 256;
        int m = fa >> 3, kq = (fa & 7) << 2;
        Asm[(kq + 0) * SA + m] = av[i].x;
        Asm[(kq + 1) * SA + m] = av[i].y;
        Asm[(kq + 2) * SA + m] = av[i].z;
        Asm[(kq + 3) * SA + m] = av[i].w;
        *(float4*)&Bsm[(fa >> 5) * SB + ((fa & 31) << 2)] = bv[i];
    }
    __syncthreads();

    float acc[2][8][4];
#pragma unroll
    for (int mt = 0; mt < 2; mt++)
#pragma unroll
        for (int nt = 0; nt < 8; nt++)
#pragma unroll
            for (int q = 0; q < 4; q++) acc[mt][nt][q] = 0.0f;

    const int aoffm = wm * 32 + g;
    const int boffn = wn * 64 + g;

    for (int st = 0; st < 16; st++) {
        const int cur = st & 1;
        if (st < 15) {
            const int k0 = (st + 1) * 32;
#pragma unroll
            for (int i = 0; i < 4; i++) {
                int fa = tid + i * 256;
                av[i] = *(const float4*)(X + (size_t)(bm + (fa >> 3)) * II + k0 + ((fa & 7) << 2));
                bv[i] = *(const float4*)(Wx + (size_t)(k0 + (fa >> 5)) * HH + bn + ((fa & 31) << 2));
            }
        }
        const float* Ac = Asm + cur * ABUF;
        const float* Bc = Bsm + cur * BBUF;
#pragma unroll
        for (int ks = 0; ks < 4; ks++) {
            const int kr0 = ks * 8 + t, kr1 = kr0 + 4;
            unsigned abig[2][4], asml[2][4], bbig[8][2], bsml[8][2];
#pragma unroll
            for (int mt = 0; mt < 2; mt++) {
                float f[4];
                f[0] = Ac[kr0 * SA + aoffm + mt * 16];
                f[1] = Ac[kr0 * SA + aoffm + mt * 16 + 8];
                f[2] = Ac[kr1 * SA + aoffm + mt * 16];
                f[3] = Ac[kr1 * SA + aoffm + mt * 16 + 8];
#pragma unroll
                for (int q = 0; q < 4; q++) {
                    unsigned bb = f2tf(f[q]);
                    abig[mt][q] = bb;
                    asml[mt][q] = f2tf(f[q] - __uint_as_float(bb));
                }
            }
#pragma unroll
            for (int nt = 0; nt < 8; nt++) {
                float q0 = Bc[kr0 * SB + boffn + nt * 8];
                float q1 = Bc[kr1 * SB + boffn + nt * 8];
                unsigned b0 = f2tf(q0), b1 = f2tf(q1);
                bbig[nt][0] = b0; bbig[nt][1] = b1;
                bsml[nt][0] = f2tf(q0 - __uint_as_float(b0));
                bsml[nt][1] = f2tf(q1 - __uint_as_float(b1));
            }
#pragma unroll
            for (int mt = 0; mt < 2; mt++)
#pragma unroll
                for (int nt = 0; nt < 8; nt++) {
                    mma_tf32(acc[mt][nt], abig[mt], bbig[nt]);
                    mma_tf32(acc[mt][nt], abig[mt], bsml[nt]);
                    mma_tf32(acc[mt][nt], asml[mt], bbig[nt]);
                }
        }
        if (st < 15) {
            const int nxt = cur ^ 1;
            __syncthreads();
#pragma unroll
            for (int i = 0; i < 4; i++) {
                int fa = tid + i * 256;
                int m = fa >> 3, kq = (fa & 7) << 2;
                Asm[nxt * ABUF + (kq + 0) * SA + m] = av[i].x;
                Asm[nxt * ABUF + (kq + 1) * SA + m] = av[i].y;
                Asm[nxt * ABUF + (kq + 2) * SA + m] = av[i].z;
                Asm[nxt * ABUF + (kq + 3) * SA + m] = av[i].w;
                *(float4*)&Bsm[nxt * BBUF + (fa >> 5) * SB + ((fa & 31) << 2)] = bv[i];
            }
            __syncthreads();
        }
    }

#pragma unroll
    for (int nt = 0; nt < 8; nt++) {
        int c = bn + wn * 64 + nt * 8 + 2 * t;
        float2 bxv = *(const float2*)&bx[c];
        float2 bhv = *(const float2*)&bh[c];
        float b0 = bxv.x + bhv.x, b1 = bxv.y + bhv.y;
#pragma unroll
        for (int mt = 0; mt < 2; mt++) {
            int r = bm + wm * 32 + mt * 16 + g;
            *(float2*)&out[(size_t)r * HH + c] =
                make_float2(acc[mt][nt][0] + b0, acc[mt][nt][1] + b1);
            *(float2*)&out[(size_t)(r + 8) * HH + c] =
                make_float2(acc[mt][nt][2] + b0, acc[mt][nt][3] + b1);
        }
    }
}

// ---------------------------------------------------------------------------
// Phase 2: recurrence — byte-identical to the round-7 kernel (2025us best).
// ---------------------------------------------------------------------------
#define PIDX(l, w_, p_) ((l) * 33 + (w_) * 4 + (p_))

__global__ __launch_bounds__(256, 1) void rnn_kernel(
    const float* __restrict__ Wh, float* __restrict__ out)
{
    __shared__ float h_Ts[HH * 8];
    __shared__ ull   part[32 * 33];

    const int tid  = threadIdx.x;
    const int lane = tid & 31;
    const int w    = tid >> 5;
    const int jq   = lane & 15;
    const int hl   = lane >> 4;
    const int kt   = (w << 1) | hl;
    const int cg   = blockIdx.x & 15;
    const int g    = blockIdx.x >> 4;
    const int jbase = cg * 32;
    const int bbase = g * 8;

    ull w2[32][2];
#pragma unroll
    for (int i = 0; i < 32; i++) {
        float2 wv = *(const float2*)&Wh[(size_t)(kt * 32 + i) * HH + jbase + jq * 2];
        w2[i][0] = pack2(wv.x, wv.x);
        w2[i][1] = pack2(wv.y, wv.y);
    }

    const int rjc = tid & 31;
    const int rp  = (tid >> 5) & 3;
    const int rb0 = bbase + rp * 2;
    const int rj  = jbase + rjc;
    const int rlane = ((rjc & 1) << 4) | (rjc >> 1);
    const bool is_red = (tid < 128);

    float* mem = out;
    float* hid = out + (size_t)BATCH * TT * HH;
    unsigned* bar = &g_bar[g * 32];

    for (int t = 0; t < TT; t++) {
        float xw0 = 0.f, xw1 = 0.f;
        if (is_red) {
            xw0 = __ldg(&mem[((size_t)rb0 * TT + t) * HH + rj]);
            xw1 = __ldg(&mem[((size_t)(rb0 + 1) * TT + t) * HH + rj]);
        }

        ull acc[2][4];
#pragma unroll
        for (int p = 0; p < 4; p++) { acc[0][p] = 0ull; acc[1][p] = 0ull; }

        if (t > 0) {
            if (lane == 0) {
                const unsigned target = (unsigned)t * 64u;
                while (ld_acq(bar) < target) { }
            }
            __syncwarp();

            const float* gsrc = &g_hT[t & 1][0][0];
#pragma unroll
            for (int i = 0; i < 4; i++) {
                int e = tid + i * 256;
                int row = e >> 1, q = e & 1;
                float4 v = __ldcg((const float4*)&gsrc[row * BATCH + bbase + q * 4]);
                *(float4*)&h_Ts[row * 8 + q * 4] = v;
            }
            __syncthreads();

            const ulonglong2* hb = (const ulonglong2*)&h_Ts[kt * 32 * 8];
#pragma unroll
            for (int i = 0; i < 32; i++) {
                ulonglong2 u0 = hb[2 * i], u1 = hb[2 * i + 1];
                ull w0 = w2[i][0], w1 = w2[i][1];
                acc[0][0] = ffma2(u0.x, w0, acc[0][0]);
                acc[0][1] = ffma2(u0.y, w0, acc[0][1]);
                acc[0][2] = ffma2(u1.x, w0, acc[0][2]);
                acc[0][3] = ffma2(u1.y, w0, acc[0][3]);
                acc[1][0] = ffma2(u0.x, w1, acc[1][0]);
                acc[1][1] = ffma2(u0.y, w1, acc[1][1]);
                acc[1][2] = ffma2(u1.x, w1, acc[1][2]);
                acc[1][3] = ffma2(u1.y, w1, acc[1][3]);
            }
        } else {
            __syncthreads();
        }

        ull v[4];
#pragma unroll
        for (int p = 0; p < 4; p++) {
            ull give = hl ? acc[0][p] : acc[1][p];
            ull got  = __shfl_xor_sync(0xFFFFFFFFu, give, 16);
            ull keep = hl ? acc[1][p] : acc[0][p];
            v[p] = fadd2(keep, got);
        }
#pragma unroll
        for (int p = 0; p < 4; p++) part[PIDX(lane, w, p)] = v[p];
        __syncthreads();

        if (is_red) {
            ull s = part[PIDX(rlane, 0, rp)];
#pragma unroll
            for (int ww = 1; ww < 8; ww++) s = fadd2(s, part[PIDX(rlane, ww, rp)]);
            float a0, a1; unpack2(s, a0, a1);
            float r0 = tanh_fast(xw0 + a0);
            float r1 = tanh_fast(xw1 + a1);
            mem[((size_t)rb0 * TT + t) * HH + rj] = r0;
            mem[((size_t)(rb0 + 1) * TT + t) * HH + rj] = r1;
            *(float2*)&g_hT[(t + 1) & 1][rj][rb0] = make_float2(r0, r1);
            if (t == TT - 1) {
                hid[(size_t)rb0 * HH + rj] = r0;
                hid[(size_t)(rb0 + 1) * HH + rj] = r1;
            }
            if (t < TT - 1) {
                __syncwarp();
                if (lane == 0) red_rel_add1(bar);
            }
        }
    }

    __syncthreads();
    if (tid == 0) {
        red_rel_add1(bar);
        if (cg == 0) {
            const unsigned full = 511u * 64u + 16u;
            while (ld_acq(bar) < full) { }
            atomicExch(bar, 0u);
        }
    }
}

// ---------------------------------------------------------------------------
extern "C" void kernel_launch(void* const* d_in, const int* in_sizes, int n_in,
                              void* d_out, int out_size) {
    const float* x  = (const float*)d_in[0];
    const float* Wx = (const float*)d_in[1];
    const float* Wh = (const float*)d_in[2];
    const float* bx = (const float*)d_in[3];
    const float* bh = (const float*)d_in[4];
    float* out = (float*)d_out;

    cudaFuncSetAttribute(gemm_tf32_kernel,
                         cudaFuncAttributeMaxDynamicSharedMemorySize, GSMEM);

    dim3 ggrid(HH / 128, (BATCH * TT) / 128);   // (4, 256)
    gemm_tf32_kernel<<<ggrid, 256, GSMEM>>>(x, Wx, bx, bh, out);
    rnn_kernel<<<128, 256>>>(Wh, out);
}